// round 2
// baseline (speedup 1.0000x reference)
#include <cuda_runtime.h>
#include <math.h>

// PINN forward + forward-mode JVPs (T, dT/dz, dT/dt, d2T/dz2)
// MLP: 3 -> 128 -> 128 -> 64 -> 1, tanh activations.
//
// R2: packed fp32 math. The 4 propagated quantities (value v, z-tangent dz,
// t-tangent dt, 2nd z-tangent dzz) are paired as (v,dz) and (dt,dzz) in
// 64-bit registers and pushed through fma.rn.f32x2 (SASS FFMA2, 2 FMA/issue).
// Shared activations are stored as float2 pairs so one LDS.64 produces a
// ready-packed operand. Weights are pre-duplicated {w,w} into __device__
// globals by an init kernel so the broadcast multiplier comes straight from
// LDG.128 as aligned 64-bit halves (no pack MOVs in the mainloop).
// tanh is computed branch-free via ex2.approx + rcp.approx (~1e-6 err).

#define TPB 512
#define PTS 32           // points per block
#define H1  128
#define H2  128
#define H3  64

typedef unsigned long long ull;

__device__ float2 g_W2d[H1 * H2];   // {w,w} duplicated pairs, 128KB
__device__ float2 g_W3d[H2 * H3];   // 64KB

__global__ void dup_weights_kernel(const float* __restrict__ W2,
                                   const float* __restrict__ W3)
{
    int i = blockIdx.x * blockDim.x + threadIdx.x;
    if (i < H1 * H2) { float w = W2[i]; g_W2d[i] = make_float2(w, w); }
    if (i < H2 * H3) { float w = W3[i]; g_W3d[i] = make_float2(w, w); }
}

__device__ __forceinline__ ull ffma2(ull a, ull b, ull c) {
    ull d;
    asm("fma.rn.f32x2 %0, %1, %2, %3;" : "=l"(d) : "l"(a), "l"(b), "l"(c));
    return d;
}

__device__ __forceinline__ ull pack2(float lo, float hi) {
    ull v;
    asm("mov.b64 %0, {%1, %2};" : "=l"(v) : "f"(lo), "f"(hi));
    return v;
}

__device__ __forceinline__ float2 unpack2(ull v) {
    float2 r;
    asm("mov.b64 {%0, %1}, %2;" : "=f"(r.x), "=f"(r.y) : "l"(v));
    return r;
}

// branch-free tanh: 1 - 2/(exp(2u)+1); exact limits at +-inf via inf/0.
__device__ __forceinline__ float fast_tanh(float u) {
    float e, r;
    asm("ex2.approx.f32 %0, %1;" : "=f"(e) : "f"(u * 2.8853900817779268f));
    asm("rcp.approx.f32 %0, %1;" : "=f"(r) : "f"(e + 1.0f));
    return fmaf(-2.0f, r, 1.0f);
}

__global__ __launch_bounds__(TPB, 1)
void pinn_fused_kernel(const float* __restrict__ x,
                       const float* __restrict__ W1, const float* __restrict__ b1,
                       const float* __restrict__ b2,
                       const float* __restrict__ b3,
                       const float* __restrict__ W4, const float* __restrict__ b4,
                       float* __restrict__ out)
{
    extern __shared__ float smem[];
    // set0: A0 = pairs {h,hdz}[128][32], B0 = pairs {hdt,hdzz}[128][32]
    float2* A0 = (float2*)smem;            // 32KB
    float2* B0 = A0 + H1 * 32;             // 32KB
    float2* A1 = B0 + H1 * 32;             // 32KB
    float2* B1 = A1 + H1 * 32;             // 32KB

    const int tid = threadIdx.x;
    const int p   = tid & 31;              // point within tile (lane)
    const int blk = blockIdx.x;

    // ---------------- Layer 1: 3 -> 128 (K=3 direct) ----------------
    for (int idx = tid; idx < PTS * H1; idx += TPB) {
        int pp = idx & 31;
        int j  = idx >> 5;
        int pg = blk * PTS + pp;
        float x0 = x[pg * 3 + 0];
        float x1 = x[pg * 3 + 1];
        float x2 = x[pg * 3 + 2];
        float w0 = __ldg(&W1[j]);
        float w1 = __ldg(&W1[H1 + j]);
        float w2 = __ldg(&W1[2 * H1 + j]);
        float u  = fmaf(x0, w0, fmaf(x1, w1, fmaf(x2, w2, __ldg(&b1[j]))));
        float h  = fast_tanh(u);
        float s  = 1.0f - h * h;
        float hdz  = s * w0;
        float hdt  = s * w1;
        float hdzz = -2.0f * h * hdz * w0;
        A0[j * 32 + pp] = make_float2(h, hdz);
        B0[j * 32 + pp] = make_float2(hdt, hdzz);
    }
    __syncthreads();

    // ---------------- Layer 2: 128 -> 128 ----------------
    // 16 warps x 8 cols; packed quantity pairs, FFMA2 mainloop.
    {
        const int j0 = (tid >> 5) * 8;
        ull acc01[8], acc23[8];
        #pragma unroll
        for (int c = 0; c < 8; c++) {
            acc01[c] = pack2(__ldg(&b2[j0 + c]), 0.0f);
            acc23[c] = 0ULL;
        }
        const ull* aA = (const ull*)A0 + p;
        const ull* aB = (const ull*)B0 + p;
        #pragma unroll 4
        for (int k = 0; k < H1; k++) {
            ull a01 = aA[k * 32];
            ull a23 = aB[k * 32];
            const float2* wrow = g_W2d + k * H2 + j0;
            ulonglong2 wa = __ldg((const ulonglong2*)(wrow + 0));
            ulonglong2 wb = __ldg((const ulonglong2*)(wrow + 2));
            ulonglong2 wc = __ldg((const ulonglong2*)(wrow + 4));
            ulonglong2 wd = __ldg((const ulonglong2*)(wrow + 6));
            acc01[0] = ffma2(a01, wa.x, acc01[0]);  acc23[0] = ffma2(a23, wa.x, acc23[0]);
            acc01[1] = ffma2(a01, wa.y, acc01[1]);  acc23[1] = ffma2(a23, wa.y, acc23[1]);
            acc01[2] = ffma2(a01, wb.x, acc01[2]);  acc23[2] = ffma2(a23, wb.x, acc23[2]);
            acc01[3] = ffma2(a01, wb.y, acc01[3]);  acc23[3] = ffma2(a23, wb.y, acc23[3]);
            acc01[4] = ffma2(a01, wc.x, acc01[4]);  acc23[4] = ffma2(a23, wc.x, acc23[4]);
            acc01[5] = ffma2(a01, wc.y, acc01[5]);  acc23[5] = ffma2(a23, wc.y, acc23[5]);
            acc01[6] = ffma2(a01, wd.x, acc01[6]);  acc23[6] = ffma2(a23, wd.x, acc23[6]);
            acc01[7] = ffma2(a01, wd.y, acc01[7]);  acc23[7] = ffma2(a23, wd.y, acc23[7]);
        }
        #pragma unroll
        for (int c = 0; c < 8; c++) {
            float2 v01 = unpack2(acc01[c]);   // x = u, y = u_dz
            float2 v23 = unpack2(acc23[c]);   // x = u_dt, y = u_dzz
            float h = fast_tanh(v01.x);
            float s = 1.0f - h * h;
            float hdz  = s * v01.y;
            float hdt  = s * v23.x;
            float hdzz = fmaf(-2.0f * h * hdz, v01.y, s * v23.y);
            A1[(j0 + c) * 32 + p] = make_float2(h, hdz);
            B1[(j0 + c) * 32 + p] = make_float2(hdt, hdzz);
        }
    }
    __syncthreads();

    // ---------------- Layer 3: 128 -> 64 ----------------
    // 16 warps x 4 cols.
    {
        const int j0 = (tid >> 5) * 4;
        ull acc01[4], acc23[4];
        #pragma unroll
        for (int c = 0; c < 4; c++) {
            acc01[c] = pack2(__ldg(&b3[j0 + c]), 0.0f);
            acc23[c] = 0ULL;
        }
        const ull* aA = (const ull*)A1 + p;
        const ull* aB = (const ull*)B1 + p;
        #pragma unroll 4
        for (int k = 0; k < H2; k++) {
            ull a01 = aA[k * 32];
            ull a23 = aB[k * 32];
            const float2* wrow = g_W3d + k * H3 + j0;
            ulonglong2 wa = __ldg((const ulonglong2*)(wrow + 0));
            ulonglong2 wb = __ldg((const ulonglong2*)(wrow + 2));
            acc01[0] = ffma2(a01, wa.x, acc01[0]);  acc23[0] = ffma2(a23, wa.x, acc23[0]);
            acc01[1] = ffma2(a01, wa.y, acc01[1]);  acc23[1] = ffma2(a23, wa.y, acc23[1]);
            acc01[2] = ffma2(a01, wb.x, acc01[2]);  acc23[2] = ffma2(a23, wb.x, acc23[2]);
            acc01[3] = ffma2(a01, wb.y, acc01[3]);  acc23[3] = ffma2(a23, wb.y, acc23[3]);
        }
        #pragma unroll
        for (int c = 0; c < 4; c++) {
            float2 v01 = unpack2(acc01[c]);
            float2 v23 = unpack2(acc23[c]);
            float h = fast_tanh(v01.x);
            float s = 1.0f - h * h;
            float hdz  = s * v01.y;
            float hdt  = s * v23.x;
            float hdzz = fmaf(-2.0f * h * hdz, v01.y, s * v23.y);
            A0[(j0 + c) * 32 + p] = make_float2(h, hdz);
            B0[(j0 + c) * 32 + p] = make_float2(hdt, hdzz);
        }
    }
    __syncthreads();

    // ---------------- Layer 4: 64 -> 1 (4 dots per point) ----------------
    if (tid < 128) {
        const int q = tid >> 5;                      // quantity 0..3
        const float2* hb = (q < 2 ? A0 : B0);
        const bool hi = (q & 1);
        float dot = (q == 0) ? __ldg(&b4[0]) : 0.0f;
        #pragma unroll
        for (int k = 0; k < H3; k++) {
            float2 v = hb[k * 32 + p];
            dot = fmaf(hi ? v.y : v.x, __ldg(&W4[k]), dot);
        }
        out[(blk * PTS + p) * 4 + q] = dot;
    }
}

extern "C" void kernel_launch(void* const* d_in, const int* in_sizes, int n_in,
                              void* d_out, int out_size)
{
    const float* x  = (const float*)d_in[0];
    const float* W1 = (const float*)d_in[1];
    const float* b1 = (const float*)d_in[2];
    const float* W2 = (const float*)d_in[3];
    const float* b2 = (const float*)d_in[4];
    const float* W3 = (const float*)d_in[5];
    const float* b3 = (const float*)d_in[6];
    const float* W4 = (const float*)d_in[7];
    const float* b4 = (const float*)d_in[8];
    float* out = (float*)d_out;

    const int N = in_sizes[0] / 3;                     // 262144
    const int smem_bytes = 4 * H1 * 32 * (int)sizeof(float2);  // 128 KB

    dup_weights_kernel<<<(H1 * H2 + 255) / 256, 256>>>(W2, W3);

    cudaFuncSetAttribute(pinn_fused_kernel,
                         cudaFuncAttributeMaxDynamicSharedMemorySize, smem_bytes);

    pinn_fused_kernel<<<N / PTS, TPB, smem_bytes>>>(
        x, W1, b1, b2, b3, W4, b4, out);
}

// round 3
// speedup vs baseline: 2.0376x; 2.0376x over previous
#include <cuda_runtime.h>
#include <math.h>

// PINN forward + forward-mode JVPs (T, dT/dz, dT/dt, d2T/dz2)
// MLP: 3 -> 128 -> 128 -> 64 -> 1, tanh activations.
//
// R3: FFMA2 (fma.rn.f32x2) with restored arithmetic intensity.
//  - 64 points per block, 2 points per thread (512 threads): weight fetch
//    amortized over 2x the FMAs vs R1/R2.
//  - The 4 JVP quantities are packed (v,dz) and (dt,dzz) into 64-bit regs;
//    shared activations stored as float2 so LDS.64 yields packed operands.
//  - Weights live in SHARED memory as scalars (96KB preloaded per block);
//    {w,w} pairs built with mov.b64 (ALU pipe, spare capacity). No global
//    duplicated-weight traffic (that saturated L1 in R2).
//  - Single in-place activation buffer (epilogue in regs + two syncs)
//    keeps total smem at 224KB.

#define TPB 512
#define PTS 64           // points per block (2 per thread)
#define H1  128
#define H2  128
#define H3  64

typedef unsigned long long ull;

__device__ __forceinline__ ull ffma2(ull a, ull b, ull c) {
    ull d;
    asm("fma.rn.f32x2 %0, %1, %2, %3;" : "=l"(d) : "l"(a), "l"(b), "l"(c));
    return d;
}
__device__ __forceinline__ ull pack2(float lo, float hi) {
    ull v;
    asm("mov.b64 %0, {%1, %2};" : "=l"(v) : "f"(lo), "f"(hi));
    return v;
}
__device__ __forceinline__ float2 unpack2(ull v) {
    float2 r;
    asm("mov.b64 {%0, %1}, %2;" : "=f"(r.x), "=f"(r.y) : "l"(v));
    return r;
}
// branch-free tanh: 1 - 2/(exp(2u)+1); exact limits at +-inf.
__device__ __forceinline__ float fast_tanh(float u) {
    float e, r;
    asm("ex2.approx.f32 %0, %1;" : "=f"(e) : "f"(u * 2.8853900817779268f));
    asm("rcp.approx.f32 %0, %1;" : "=f"(r) : "f"(e + 1.0f));
    return fmaf(-2.0f, r, 1.0f);
}

// tanh JVP epilogue: given packed u-pairs, produce packed h-pairs.
__device__ __forceinline__ void tanh_jvp(ull u01, ull u23, ull* h01, ull* h23) {
    float2 v01 = unpack2(u01);   // x=u, y=u_dz
    float2 v23 = unpack2(u23);   // x=u_dt, y=u_dzz
    float h = fast_tanh(v01.x);
    float s = 1.0f - h * h;
    float hdz  = s * v01.y;
    float hdt  = s * v23.x;
    float hdzz = fmaf(-2.0f * h * hdz, v01.y, s * v23.y);
    *h01 = pack2(h, hdz);
    *h23 = pack2(hdt, hdzz);
}

__global__ __launch_bounds__(TPB, 1)
void pinn_fused_kernel(const float* __restrict__ x,
                       const float* __restrict__ W1, const float* __restrict__ b1,
                       const float* __restrict__ W2, const float* __restrict__ b2,
                       const float* __restrict__ W3, const float* __restrict__ b3,
                       const float* __restrict__ W4, const float* __restrict__ b4,
                       float* __restrict__ out)
{
    extern __shared__ float smem[];
    // A: {h,hdz}[128 units][64 pts] float2 = 64KB
    // B: {hdt,hdzz}[128][64] float2        = 64KB
    // W2s: 16384 floats = 64KB ; W3s: 8192 floats = 32KB
    float2* A   = (float2*)smem;                    // 64KB
    float2* B   = A + H1 * PTS;                     // 64KB
    float*  W2s = (float*)(B + H1 * PTS);           // 64KB
    float*  W3s = W2s + H1 * H2;                    // 32KB

    const int tid  = threadIdx.x;
    const int lane = tid & 31;
    const int blk  = blockIdx.x;

    // -------- preload weights into smem (vectorized) --------
    {
        const float4* s4 = (const float4*)W2;
        float4* d4 = (float4*)W2s;
        #pragma unroll
        for (int i = 0; i < (H1 * H2 / 4) / TPB; i++)
            d4[tid + i * TPB] = __ldg(&s4[tid + i * TPB]);
        const float4* s3 = (const float4*)W3;
        float4* d3 = (float4*)W3s;
        #pragma unroll
        for (int i = 0; i < (H2 * H3 / 4) / TPB; i++)
            d3[tid + i * TPB] = __ldg(&s3[tid + i * TPB]);
    }

    // ---------------- Layer 1: 3 -> 128 (K=3 direct) ----------------
    #pragma unroll
    for (int it = 0; it < (PTS * H1) / TPB; it++) {
        int idx = tid + it * TPB;
        int pp = idx & (PTS - 1);
        int j  = idx / PTS;
        int pg = blk * PTS + pp;
        float x0 = x[pg * 3 + 0];
        float x1 = x[pg * 3 + 1];
        float x2 = x[pg * 3 + 2];
        float w0 = __ldg(&W1[j]);
        float w1 = __ldg(&W1[H1 + j]);
        float w2 = __ldg(&W1[2 * H1 + j]);
        float u  = fmaf(x0, w0, fmaf(x1, w1, fmaf(x2, w2, __ldg(&b1[j]))));
        float h  = fast_tanh(u);
        float s  = 1.0f - h * h;
        float hdz  = s * w0;
        float hdt  = s * w1;
        float hdzz = -2.0f * h * hdz * w0;
        A[j * PTS + pp] = make_float2(h, hdz);
        B[j * PTS + pp] = make_float2(hdt, hdzz);
    }
    __syncthreads();

    // ---------------- Layer 2: 128 -> 128 (in-place) ----------------
    // 16 warps x 8 cols; each thread: 2 points (lane, lane+32), 8 cols.
    {
        const int j0 = (tid >> 5) * 8;
        ull acc01a[8], acc23a[8], acc01b[8], acc23b[8];
        #pragma unroll
        for (int c = 0; c < 8; c++) {
            ull bias = pack2(b2[j0 + c], 0.0f);
            acc01a[c] = bias;  acc01b[c] = bias;
            acc23a[c] = 0ULL;  acc23b[c] = 0ULL;
        }
        const ull* aA = (const ull*)A;
        const ull* aB = (const ull*)B;
        #pragma unroll 2
        for (int k = 0; k < H1; k++) {
            ull a01a = aA[k * PTS + lane];
            ull a23a = aB[k * PTS + lane];
            ull a01b = aA[k * PTS + lane + 32];
            ull a23b = aB[k * PTS + lane + 32];
            float4 wA = *(const float4*)(W2s + k * H2 + j0);
            float4 wB = *(const float4*)(W2s + k * H2 + j0 + 4);
            ull w0 = pack2(wA.x, wA.x), w1 = pack2(wA.y, wA.y);
            ull w2 = pack2(wA.z, wA.z), w3 = pack2(wA.w, wA.w);
            ull w4 = pack2(wB.x, wB.x), w5 = pack2(wB.y, wB.y);
            ull w6 = pack2(wB.z, wB.z), w7 = pack2(wB.w, wB.w);
            acc01a[0] = ffma2(a01a, w0, acc01a[0]);  acc23a[0] = ffma2(a23a, w0, acc23a[0]);
            acc01b[0] = ffma2(a01b, w0, acc01b[0]);  acc23b[0] = ffma2(a23b, w0, acc23b[0]);
            acc01a[1] = ffma2(a01a, w1, acc01a[1]);  acc23a[1] = ffma2(a23a, w1, acc23a[1]);
            acc01b[1] = ffma2(a01b, w1, acc01b[1]);  acc23b[1] = ffma2(a23b, w1, acc23b[1]);
            acc01a[2] = ffma2(a01a, w2, acc01a[2]);  acc23a[2] = ffma2(a23a, w2, acc23a[2]);
            acc01b[2] = ffma2(a01b, w2, acc01b[2]);  acc23b[2] = ffma2(a23b, w2, acc23b[2]);
            acc01a[3] = ffma2(a01a, w3, acc01a[3]);  acc23a[3] = ffma2(a23a, w3, acc23a[3]);
            acc01b[3] = ffma2(a01b, w3, acc01b[3]);  acc23b[3] = ffma2(a23b, w3, acc23b[3]);
            acc01a[4] = ffma2(a01a, w4, acc01a[4]);  acc23a[4] = ffma2(a23a, w4, acc23a[4]);
            acc01b[4] = ffma2(a01b, w4, acc01b[4]);  acc23b[4] = ffma2(a23b, w4, acc23b[4]);
            acc01a[5] = ffma2(a01a, w5, acc01a[5]);  acc23a[5] = ffma2(a23a, w5, acc23a[5]);
            acc01b[5] = ffma2(a01b, w5, acc01b[5]);  acc23b[5] = ffma2(a23b, w5, acc23b[5]);
            acc01a[6] = ffma2(a01a, w6, acc01a[6]);  acc23a[6] = ffma2(a23a, w6, acc23a[6]);
            acc01b[6] = ffma2(a01b, w6, acc01b[6]);  acc23b[6] = ffma2(a23b, w6, acc23b[6]);
            acc01a[7] = ffma2(a01a, w7, acc01a[7]);  acc23a[7] = ffma2(a23a, w7, acc23a[7]);
            acc01b[7] = ffma2(a01b, w7, acc01b[7]);  acc23b[7] = ffma2(a23b, w7, acc23b[7]);
        }
        // epilogue in registers
        ull h01a[8], h23a[8], h01b[8], h23b[8];
        #pragma unroll
        for (int c = 0; c < 8; c++) {
            tanh_jvp(acc01a[c], acc23a[c], &h01a[c], &h23a[c]);
            tanh_jvp(acc01b[c], acc23b[c], &h01b[c], &h23b[c]);
        }
        __syncthreads();   // everyone done READING layer-1 activations
        ull* oA = (ull*)A;
        ull* oB = (ull*)B;
        #pragma unroll
        for (int c = 0; c < 8; c++) {
            int j = j0 + c;
            oA[j * PTS + lane]      = h01a[c];
            oB[j * PTS + lane]      = h23a[c];
            oA[j * PTS + lane + 32] = h01b[c];
            oB[j * PTS + lane + 32] = h23b[c];
        }
    }
    __syncthreads();

    // ---------------- Layer 3: 128 -> 64 (in-place) ----------------
    // 16 warps x 4 cols; 2 points per thread.
    {
        const int j0 = (tid >> 5) * 4;
        ull acc01a[4], acc23a[4], acc01b[4], acc23b[4];
        #pragma unroll
        for (int c = 0; c < 4; c++) {
            ull bias = pack2(b3[j0 + c], 0.0f);
            acc01a[c] = bias;  acc01b[c] = bias;
            acc23a[c] = 0ULL;  acc23b[c] = 0ULL;
        }
        const ull* aA = (const ull*)A;
        const ull* aB = (const ull*)B;
        #pragma unroll 2
        for (int k = 0; k < H2; k++) {
            ull a01a = aA[k * PTS + lane];
            ull a23a = aB[k * PTS + lane];
            ull a01b = aA[k * PTS + lane + 32];
            ull a23b = aB[k * PTS + lane + 32];
            float4 wA = *(const float4*)(W3s + k * H3 + j0);
            ull w0 = pack2(wA.x, wA.x), w1 = pack2(wA.y, wA.y);
            ull w2 = pack2(wA.z, wA.z), w3 = pack2(wA.w, wA.w);
            acc01a[0] = ffma2(a01a, w0, acc01a[0]);  acc23a[0] = ffma2(a23a, w0, acc23a[0]);
            acc01b[0] = ffma2(a01b, w0, acc01b[0]);  acc23b[0] = ffma2(a23b, w0, acc23b[0]);
            acc01a[1] = ffma2(a01a, w1, acc01a[1]);  acc23a[1] = ffma2(a23a, w1, acc23a[1]);
            acc01b[1] = ffma2(a01b, w1, acc01b[1]);  acc23b[1] = ffma2(a23b, w1, acc23b[1]);
            acc01a[2] = ffma2(a01a, w2, acc01a[2]);  acc23a[2] = ffma2(a23a, w2, acc23a[2]);
            acc01b[2] = ffma2(a01b, w2, acc01b[2]);  acc23b[2] = ffma2(a23b, w2, acc23b[2]);
            acc01a[3] = ffma2(a01a, w3, acc01a[3]);  acc23a[3] = ffma2(a23a, w3, acc23a[3]);
            acc01b[3] = ffma2(a01b, w3, acc01b[3]);  acc23b[3] = ffma2(a23b, w3, acc23b[3]);
        }
        ull h01a[4], h23a[4], h01b[4], h23b[4];
        #pragma unroll
        for (int c = 0; c < 4; c++) {
            tanh_jvp(acc01a[c], acc23a[c], &h01a[c], &h23a[c]);
            tanh_jvp(acc01b[c], acc23b[c], &h01b[c], &h23b[c]);
        }
        __syncthreads();   // everyone done READING layer-2 activations
        ull* oA = (ull*)A;
        ull* oB = (ull*)B;
        #pragma unroll
        for (int c = 0; c < 4; c++) {
            int j = j0 + c;
            oA[j * PTS + lane]      = h01a[c];
            oB[j * PTS + lane]      = h23a[c];
            oA[j * PTS + lane + 32] = h01b[c];
            oB[j * PTS + lane + 32] = h23b[c];
        }
    }
    __syncthreads();

    // ---------------- Layer 4: 64 -> 1 (4 dots per point) ----------------
    if (tid < 256) {
        const int q = tid >> 6;            // quantity 0..3
        const int p = tid & 63;            // point
        const float2* hb = (q < 2 ? A : B);
        const bool hi = (q & 1);
        float dot = (q == 0) ? __ldg(&b4[0]) : 0.0f;
        #pragma unroll
        for (int k = 0; k < H3; k++) {
            float2 v = hb[k * PTS + p];
            dot = fmaf(hi ? v.y : v.x, __ldg(&W4[k]), dot);
        }
        out[(blk * PTS + p) * 4 + q] = dot;
    }
}

extern "C" void kernel_launch(void* const* d_in, const int* in_sizes, int n_in,
                              void* d_out, int out_size)
{
    const float* x  = (const float*)d_in[0];
    const float* W1 = (const float*)d_in[1];
    const float* b1 = (const float*)d_in[2];
    const float* W2 = (const float*)d_in[3];
    const float* b2 = (const float*)d_in[4];
    const float* W3 = (const float*)d_in[5];
    const float* b3 = (const float*)d_in[6];
    const float* W4 = (const float*)d_in[7];
    const float* b4 = (const float*)d_in[8];
    float* out = (float*)d_out;

    const int N = in_sizes[0] / 3;  // 262144
    // A(64KB) + B(64KB) + W2s(64KB) + W3s(32KB) = 224KB
    const int smem_bytes = (2 * H1 * PTS * 2 + H1 * H2 + H2 * H3) * (int)sizeof(float);

    cudaFuncSetAttribute(pinn_fused_kernel,
                         cudaFuncAttributeMaxDynamicSharedMemorySize, smem_bytes);

    pinn_fused_kernel<<<N / PTS, TPB, smem_bytes>>>(
        x, W1, b1, W2, b2, W3, b3, W4, b4, out);
}